// round 2
// baseline (speedup 1.0000x reference)
#include <cuda_runtime.h>
#include <cstdint>

// Problem constants (fixed by the reference)
#define B_    64
#define T_    24
#define NV_   1024
#define C_    64
#define DPW_  7
#define TPD_  288
#define TILE_ 1536              // C_*T_ floats per (b,n) slab = 6144 bytes
#define REP_  8                 // tile replicas in SMEM -> 48KB bulk-store granularity
#define VPB_  64                // vertices per block
#define OPS_  (VPB_ / REP_)     // 8 bulk stores per block
#define THREADS_ 512
#define BULK_BYTES_ (REP_ * TILE_ * 4)   // 49152 bytes per cp.async.bulk

__global__ __launch_bounds__(THREADS_)
void dte_kernel(const int* __restrict__ t,
                const float* __restrict__ W,
                float* __restrict__ out) {
    __shared__ alignas(128) float e[REP_ * TILE_];   // 48 KB

    const int b      = blockIdx.x >> 4;     // / (NV_/VPB_) == /16
    const int nchunk = blockIdx.x & 15;
    const int tid    = threadIdx.x;

    // Build base tile e[c][t] = W[dow_t][c] + W[DPW+tod_t][c] (output layout).
    // t/W reads are tiny and L1-cached; no index smem needed.
    for (int idx = tid; idx < TILE_; idx += THREADS_) {
        int c  = idx / T_;
        int ti = idx - c * T_;
        int dow = t[(b * T_ + ti) * 2 + 0] % DPW_;
        int tod = t[(b * T_ + ti) * 2 + 1] % TPD_;
        e[idx] = W[dow * C_ + c] + W[(DPW_ + tod) * C_ + c];
    }
    __syncthreads();

    // Replicate tile to REP_ copies (consecutive vertex slabs are contiguous in gmem).
    float4* e4 = reinterpret_cast<float4*>(e);
    for (int idx = tid; idx < TILE_ / 4; idx += THREADS_) {
        float4 v = e4[idx];
        #pragma unroll
        for (int r = 1; r < REP_; r++) e4[r * (TILE_ / 4) + idx] = v;
    }

    // Make generic-proxy smem writes visible to the async (TMA) proxy.
    asm volatile("fence.proxy.async.shared::cta;" ::: "memory");
    __syncthreads();

    if (tid == 0) {
        uint32_t src;
        asm("{ .reg .u64 tt; cvta.to.shared.u64 tt, %1; cvt.u32.u64 %0, tt; }"
            : "=r"(src) : "l"(e));
        float* dst = out + ((size_t)b * NV_ + (size_t)nchunk * VPB_) * TILE_;
        const unsigned nbytes = BULK_BYTES_;
        #pragma unroll
        for (int op = 0; op < OPS_; op++) {
            asm volatile(
                "cp.async.bulk.global.shared::cta.bulk_group [%0], [%1], %2;"
                :: "l"(dst + (size_t)op * REP_ * TILE_), "r"(src), "r"(nbytes)
                : "memory");
        }
        asm volatile("cp.async.bulk.commit_group;" ::: "memory");
        // Must fully drain before CTA exit (smem is reclaimed on exit).
        asm volatile("cp.async.bulk.wait_group 0;" ::: "memory");
    }
}

extern "C" void kernel_launch(void* const* d_in, const int* in_sizes, int n_in,
                              void* d_out, int out_size) {
    const int*   t = (const int*)d_in[0];    // [B, T, 2] int32
    const float* W = (const float*)d_in[1];  // [DPW+TPD, C] float32
    float* out = (float*)d_out;              // [B, N, C, T] float32

    dim3 grid(B_ * (NV_ / VPB_));            // 1024 blocks
    dte_kernel<<<grid, THREADS_>>>(t, W, out);
}

// round 3
// speedup vs baseline: 1.0134x; 1.0134x over previous
#include <cuda_runtime.h>
#include <cstdint>

// Problem constants (fixed by the reference)
#define B_    64
#define T_    24
#define NV_   1024
#define C_    64
#define DPW_  7
#define TPD_  288
#define TILE_   (C_ * T_)        // 1536 floats = 6144 bytes per (b,n) slab
#define TILE8_  (TILE_ / 8)      // 192 float8 chunks
#define VPB_    32               // vertices per block
#define THREADS_ 384             // 2 * TILE8_ -> 2 vertex slabs per store wave

__global__ __launch_bounds__(THREADS_)
void dte_kernel(const int* __restrict__ t,
                const float* __restrict__ W,
                float* __restrict__ out) {
    __shared__ float e[TILE_];
    __shared__ int dow_s[T_];
    __shared__ int tod_s[T_];

    const int b      = blockIdx.x >> 5;          // / (NV_/VPB_) == /32
    const int nchunk = blockIdx.x & 31;
    const int tid    = threadIdx.x;

    // Load the 24 (dow, tod) index pairs for this batch
    if (tid < T_) {
        int dow = t[(b * T_ + tid) * 2 + 0] % DPW_;
        int tod = t[(b * T_ + tid) * 2 + 1] % TPD_;
        dow_s[tid] = dow * C_;
        tod_s[tid] = (DPW_ + tod) * C_;
    }
    __syncthreads();

    // Build e[c][t] = W[dow_t][c] + W[DPW+tod_t][c]  (c-major, t-minor = output layout)
    for (int idx = tid; idx < TILE_; idx += THREADS_) {
        int c  = idx / T_;
        int ti = idx - c * T_;
        e[idx] = W[dow_s[ti] + c] + W[tod_s[ti] + c];
    }
    __syncthreads();

    // Thread -> (sub-vertex, float8 chunk). T_=24 is a multiple of 8, so each
    // float8 chunk stays within one c-row; 32B alignment holds everywhere.
    const int vsub = tid / TILE8_;       // 0 or 1
    const int j    = tid - vsub * TILE8_;

    const float4 lo = reinterpret_cast<const float4*>(e)[2 * j + 0];
    const float4 hi = reinterpret_cast<const float4*>(e)[2 * j + 1];

    const float* base = out + ((size_t)b * NV_ + (size_t)nchunk * VPB_ + vsub) * TILE_
                            + (size_t)j * 8;

    #pragma unroll
    for (int v = 0; v < VPB_; v += 2) {
        const float* p = base + (size_t)v * TILE_;
        asm volatile(
            "st.global.cs.v8.f32 [%0], {%1,%2,%3,%4,%5,%6,%7,%8};"
            :: "l"(p),
               "f"(lo.x), "f"(lo.y), "f"(lo.z), "f"(lo.w),
               "f"(hi.x), "f"(hi.y), "f"(hi.z), "f"(hi.w)
            : "memory");
    }
}

extern "C" void kernel_launch(void* const* d_in, const int* in_sizes, int n_in,
                              void* d_out, int out_size) {
    const int*   t = (const int*)d_in[0];    // [B, T, 2] int32
    const float* W = (const float*)d_in[1];  // [DPW+TPD, C] float32
    float* out = (float*)d_out;              // [B, N, C, T] float32

    dim3 grid(B_ * (NV_ / VPB_));            // 2048 blocks
    dte_kernel<<<grid, THREADS_>>>(t, W, out);
}